// round 1
// baseline (speedup 1.0000x reference)
#include <cuda_runtime.h>

#define BB 4096
#define TT 512
#define HH 32

typedef unsigned long long u64;

__device__ __forceinline__ u64 pk2(float lo, float hi) {
    u64 r; asm("mov.b64 %0, {%1,%2};" : "=l"(r) : "f"(lo), "f"(hi)); return r;
}
__device__ __forceinline__ void unpk2(u64 v, float& a, float& b) {
    asm("mov.b64 {%0,%1}, %2;" : "=f"(a), "=f"(b) : "l"(v));
}
// Packed f32x2 FMA (Blackwell-only full-rate path; ptxas never auto-fuses this)
__device__ __forceinline__ u64 ffma2(u64 a, u64 b, u64 c) {
    u64 d; asm("fma.rn.f32x2 %0, %1, %2, %3;" : "=l"(d) : "l"(a), "l"(b), "l"(c));
    return d;
}

// Accurate-enough fast tanh: MUFU.EX2 + MUFU.RCP path, rel err ~1e-6
__device__ __forceinline__ float tanh_fast(float v) {
    float e = __expf(2.0f * v);
    return 1.0f - __fdividef(2.0f, e + 1.0f);
}

__global__ void __launch_bounds__(256)
rnn2_kernel(const float* __restrict__ x,       // [B, T, 1]
            const float* __restrict__ hstate,  // [2, B, H]
            const float* __restrict__ Wih0,    // [H, 1]
            const float* __restrict__ Whh0,    // [H, H]
            const float* __restrict__ bih0, const float* __restrict__ bhh0,
            const float* __restrict__ Wih1,    // [H, H]
            const float* __restrict__ Whh1,    // [H, H]
            const float* __restrict__ bih1, const float* __restrict__ bhh1,
            const float* __restrict__ Wfc,     // [1, H]
            const float* __restrict__ bfc,     // [1]
            float* __restrict__ out)           // [B] pred ++ [2,B,H] h_new
{
    // [warp][layer][double-buffer][k] — each row is 128B, all lanes of a warp
    // read the same address -> broadcast, conflict-free LDS.128
    __shared__ __align__(16) float sh[8][2][2][HH];

    const int w = threadIdx.x >> 5;
    const int j = threadIdx.x & 31;
    const int b = blockIdx.x * 8 + w;

    // Weight rows for this output neuron, pre-packed as f32x2 pairs (k, k+1).
    // 48 x 64-bit = 96 registers — the register-resident floor.
    u64 w0[16], wi1[16], wh1[16];
    {
        const u64* p = (const u64*)(Whh0 + j * HH);
        #pragma unroll
        for (int i = 0; i < 16; i++) w0[i] = p[i];
        p = (const u64*)(Wih1 + j * HH);
        #pragma unroll
        for (int i = 0; i < 16; i++) wi1[i] = p[i];
        p = (const u64*)(Whh1 + j * HH);
        #pragma unroll
        for (int i = 0; i < 16; i++) wh1[i] = p[i];
    }
    const float wx0 = Wih0[j];
    const float bb0 = bih0[j] + bhh0[j];
    const float bb1 = bih1[j] + bhh1[j];

    // Initial hidden state into buffer 0
    sh[w][0][0][j] = hstate[(size_t)b * HH + j];
    sh[w][1][0][j] = hstate[(size_t)BB * HH + (size_t)b * HH + j];
    __syncwarp();

    const float* xb = x + (size_t)b * TT;
    float xv = xb[0];  // software prefetch of x_t (uniform across warp, L1-resident)
    float h0n = 0.f, h1n = 0.f;

    #pragma unroll 1
    for (int t = 0; t < TT; t += 2) {
        #pragma unroll
        for (int s = 0; s < 2; s++) {      // unrolled x2 -> compile-time buffer parity
            const int pb = s;              // read buffer
            const int nb = s ^ 1;          // write buffer
            const float xt = xv;
            int tn = t + s + 1; if (tn > TT - 1) tn = TT - 1;
            xv = xb[tn];

            // ---- layer 0: h0' = tanh(Wih0*x + b + Whh0 @ h0) ----
            u64 acc  = pk2(0.f, 0.f);
            u64 accb = pk2(0.f, 0.f);
            const ulonglong2* hp = (const ulonglong2*)sh[w][0][pb];
            #pragma unroll
            for (int i = 0; i < 8; i++) {
                ulonglong2 v = hp[i];                 // h[4i..4i+3] via LDS.128 broadcast
                acc  = ffma2(w0[2*i],     v.x, acc);
                accb = ffma2(w0[2*i + 1], v.y, accb);
            }
            float a0, a1, a2, a3;
            unpk2(acc, a0, a1); unpk2(accb, a2, a3);
            float pre0 = (a0 + a1) + (a2 + a3) + fmaf(wx0, xt, bb0);
            h0n = tanh_fast(pre0);
            sh[w][0][nb][j] = h0n;
            __syncwarp();

            // ---- layer 1: h1' = tanh(Wih1 @ h0' + b + Whh1 @ h1) ----
            acc  = pk2(0.f, 0.f);
            accb = pk2(0.f, 0.f);
            const ulonglong2* hn  = (const ulonglong2*)sh[w][0][nb];
            const ulonglong2* h1p = (const ulonglong2*)sh[w][1][pb];
            #pragma unroll
            for (int i = 0; i < 8; i++) {
                ulonglong2 v = hn[i];
                acc  = ffma2(wi1[2*i],     v.x, acc);
                accb = ffma2(wi1[2*i + 1], v.y, accb);
            }
            #pragma unroll
            for (int i = 0; i < 8; i++) {
                ulonglong2 v = h1p[i];
                acc  = ffma2(wh1[2*i],     v.x, acc);
                accb = ffma2(wh1[2*i + 1], v.y, accb);
            }
            unpk2(acc, a0, a1); unpk2(accb, a2, a3);
            float pre1 = (a0 + a1) + (a2 + a3) + bb1;
            h1n = tanh_fast(pre1);
            sh[w][1][nb][j] = h1n;
            __syncwarp();
        }
    }

    // ---- outputs ----
    const size_t ob = (size_t)b * HH + j;
    out[BB + ob]                      = h0n;   // h_new[0]
    out[BB + (size_t)BB * HH + ob]    = h1n;   // h_new[1]

    // pred[b] = Wfc . h1_last + bfc  (intra-warp butterfly reduction)
    float p = Wfc[j] * h1n;
    #pragma unroll
    for (int off = 16; off; off >>= 1)
        p += __shfl_xor_sync(0xffffffffu, p, off);
    if (j == 0) out[b] = p + bfc[0];
}

extern "C" void kernel_launch(void* const* d_in, const int* in_sizes, int n_in,
                              void* d_out, int out_size) {
    const float* x     = (const float*)d_in[0];
    const float* hs    = (const float*)d_in[1];
    const float* Wih0  = (const float*)d_in[2];
    const float* Whh0  = (const float*)d_in[3];
    const float* bih0  = (const float*)d_in[4];
    const float* bhh0  = (const float*)d_in[5];
    const float* Wih1  = (const float*)d_in[6];
    const float* Whh1  = (const float*)d_in[7];
    const float* bih1  = (const float*)d_in[8];
    const float* bhh1  = (const float*)d_in[9];
    const float* Wfc   = (const float*)d_in[10];
    const float* bfc   = (const float*)d_in[11];
    float* out = (float*)d_out;

    rnn2_kernel<<<BB / 8, 256>>>(x, hs, Wih0, Whh0, bih0, bhh0,
                                 Wih1, Whh1, bih1, bhh1, Wfc, bfc, out);
}

// round 2
// speedup vs baseline: 1.3070x; 1.3070x over previous
#include <cuda_runtime.h>

#define BB 4096
#define TT 512
#define HH 32
#define NB 4      // batches per warp (ILP streams sharing the weight registers)

typedef unsigned long long u64;

__device__ __forceinline__ u64 pk2(float lo, float hi) {
    u64 r; asm("mov.b64 %0, {%1,%2};" : "=l"(r) : "f"(lo), "f"(hi)); return r;
}
__device__ __forceinline__ void unpk2(u64 v, float& a, float& b) {
    asm("mov.b64 {%0,%1}, %2;" : "=f"(a), "=f"(b) : "l"(v));
}
// Packed f32x2 FMA (Blackwell full-rate path; ptxas never auto-fuses this)
__device__ __forceinline__ u64 ffma2(u64 a, u64 b, u64 c) {
    u64 d; asm("fma.rn.f32x2 %0, %1, %2, %3;" : "=l"(d) : "l"(a), "l"(b), "l"(c));
    return d;
}

// Accurate fast tanh: MUFU.EX2 + MUFU.RCP path, rel err ~1e-6
__device__ __forceinline__ float tanh_fast(float v) {
    float e = __expf(2.0f * v);
    return 1.0f - __fdividef(2.0f, e + 1.0f);
}

__global__ void __launch_bounds__(256)
rnn2_kernel(const float* __restrict__ x,       // [B, T, 1]
            const float* __restrict__ hstate,  // [2, B, H]
            const float* __restrict__ Wih0,    // [H, 1]
            const float* __restrict__ Whh0,    // [H, H]
            const float* __restrict__ bih0, const float* __restrict__ bhh0,
            const float* __restrict__ Wih1,    // [H, H]
            const float* __restrict__ Whh1,    // [H, H]
            const float* __restrict__ bih1, const float* __restrict__ bhh1,
            const float* __restrict__ Wfc,     // [1, H]
            const float* __restrict__ bfc,     // [1]
            float* __restrict__ out)           // [B] pred ++ [2,B,H] h_new
{
    // [warp][batch][layer][double-buffer][k] — each 32-float row is 128B;
    // all lanes read the same 16B -> broadcast, conflict-free LDS.128.
    // Writes are lane j -> word j: conflict-free.
    __shared__ __align__(16) float sh[8][NB][2][2][HH];

    const int w  = threadIdx.x >> 5;
    const int j  = threadIdx.x & 31;
    const int b0 = (blockIdx.x * 8 + w) * NB;

    // Weight rows for output neuron j, pre-packed as f32x2 pairs (k, k+1).
    // 48 x 64-bit = 96 registers, SHARED across all NB batch streams.
    u64 w0[16], wi1[16], wh1[16];
    {
        const u64* p = (const u64*)(Whh0 + j * HH);
        #pragma unroll
        for (int i = 0; i < 16; i++) w0[i] = p[i];
        p = (const u64*)(Wih1 + j * HH);
        #pragma unroll
        for (int i = 0; i < 16; i++) wi1[i] = p[i];
        p = (const u64*)(Whh1 + j * HH);
        #pragma unroll
        for (int i = 0; i < 16; i++) wh1[i] = p[i];
    }
    const float wx0 = Wih0[j];
    const float bb0 = bih0[j] + bhh0[j];
    const float bb1 = bih1[j] + bhh1[j];

    // Initial hidden states into buffer 0
    #pragma unroll
    for (int bi = 0; bi < NB; bi++) {
        sh[w][bi][0][0][j] = hstate[(size_t)(b0 + bi) * HH + j];
        sh[w][bi][1][0][j] = hstate[(size_t)BB * HH + (size_t)(b0 + bi) * HH + j];
    }
    __syncwarp();

    const float* xb[NB];
    float xv[NB];
    #pragma unroll
    for (int bi = 0; bi < NB; bi++) {
        xb[bi] = x + (size_t)(b0 + bi) * TT;
        xv[bi] = xb[bi][0];          // software prefetch (uniform across warp)
    }

    float h0n[NB], h1n[NB];

    #pragma unroll 1
    for (int t = 0; t < TT; t += 2) {
        #pragma unroll
        for (int s = 0; s < 2; s++) {      // unrolled x2 -> compile-time buffer parity
            const int pb = s;              // read buffer
            const int nbuf = s ^ 1;        // write buffer
            int tn = t + s + 1; if (tn > TT - 1) tn = TT - 1;

            u64 acc[NB], accb[NB];
            float xt[NB];
            #pragma unroll
            for (int bi = 0; bi < NB; bi++) {
                acc[bi]  = pk2(0.f, 0.f);
                accb[bi] = pk2(0.f, 0.f);
                xt[bi] = xv[bi];
                xv[bi] = xb[bi][tn];
            }

            // ---- layer 0: h0' = tanh(Wih0*x + b + Whh0 @ h0) ----
            #pragma unroll
            for (int i = 0; i < 8; i++) {
                #pragma unroll
                for (int bi = 0; bi < NB; bi++) {
                    ulonglong2 v = ((const ulonglong2*)sh[w][bi][0][pb])[i];
                    acc[bi]  = ffma2(w0[2*i],     v.x, acc[bi]);
                    accb[bi] = ffma2(w0[2*i + 1], v.y, accb[bi]);
                }
            }
            #pragma unroll
            for (int bi = 0; bi < NB; bi++) {
                float a0, a1, a2, a3;
                unpk2(acc[bi], a0, a1); unpk2(accb[bi], a2, a3);
                float pre0 = (a0 + a1) + (a2 + a3) + fmaf(wx0, xt[bi], bb0);
                h0n[bi] = tanh_fast(pre0);
                sh[w][bi][0][nbuf][j] = h0n[bi];
            }
            __syncwarp();

            // ---- layer 1: h1' = tanh(Wih1 @ h0' + b + Whh1 @ h1) ----
            #pragma unroll
            for (int bi = 0; bi < NB; bi++) {
                acc[bi]  = pk2(0.f, 0.f);
                accb[bi] = pk2(0.f, 0.f);
            }
            #pragma unroll
            for (int i = 0; i < 8; i++) {
                #pragma unroll
                for (int bi = 0; bi < NB; bi++) {
                    ulonglong2 v = ((const ulonglong2*)sh[w][bi][0][nbuf])[i];
                    acc[bi]  = ffma2(wi1[2*i],     v.x, acc[bi]);
                    accb[bi] = ffma2(wi1[2*i + 1], v.y, accb[bi]);
                }
            }
            #pragma unroll
            for (int i = 0; i < 8; i++) {
                #pragma unroll
                for (int bi = 0; bi < NB; bi++) {
                    ulonglong2 v = ((const ulonglong2*)sh[w][bi][1][pb])[i];
                    acc[bi]  = ffma2(wh1[2*i],     v.x, acc[bi]);
                    accb[bi] = ffma2(wh1[2*i + 1], v.y, accb[bi]);
                }
            }
            #pragma unroll
            for (int bi = 0; bi < NB; bi++) {
                float a0, a1, a2, a3;
                unpk2(acc[bi], a0, a1); unpk2(accb[bi], a2, a3);
                float pre1 = (a0 + a1) + (a2 + a3) + bb1;
                h1n[bi] = tanh_fast(pre1);
                sh[w][bi][1][nbuf][j] = h1n[bi];
            }
            __syncwarp();
        }
    }

    // ---- outputs ----
    #pragma unroll
    for (int bi = 0; bi < NB; bi++) {
        const size_t ob = (size_t)(b0 + bi) * HH + j;
        out[BB + ob]                   = h0n[bi];   // h_new[0]
        out[BB + (size_t)BB * HH + ob] = h1n[bi];   // h_new[1]

        // pred[b] = Wfc . h1_last + bfc (intra-warp butterfly reduction)
        float p = Wfc[j] * h1n[bi];
        #pragma unroll
        for (int off = 16; off; off >>= 1)
            p += __shfl_xor_sync(0xffffffffu, p, off);
        if (j == 0) out[b0 + bi] = p + bfc[0];
    }
}

extern "C" void kernel_launch(void* const* d_in, const int* in_sizes, int n_in,
                              void* d_out, int out_size) {
    const float* x     = (const float*)d_in[0];
    const float* hs    = (const float*)d_in[1];
    const float* Wih0  = (const float*)d_in[2];
    const float* Whh0  = (const float*)d_in[3];
    const float* bih0  = (const float*)d_in[4];
    const float* bhh0  = (const float*)d_in[5];
    const float* Wih1  = (const float*)d_in[6];
    const float* Whh1  = (const float*)d_in[7];
    const float* bih1  = (const float*)d_in[8];
    const float* bhh1  = (const float*)d_in[9];
    const float* Wfc   = (const float*)d_in[10];
    const float* bfc   = (const float*)d_in[11];
    float* out = (float*)d_out;

    rnn2_kernel<<<BB / (8 * NB), 256>>>(x, hs, Wih0, Whh0, bih0, bhh0,
                                        Wih1, Whh1, bih1, bhh1, Wfc, bfc, out);
}

// round 3
// speedup vs baseline: 1.4863x; 1.1372x over previous
#include <cuda_runtime.h>

#define BB 4096
#define TT 512
#define HH 32
#define NB 4      // batch streams per warp (ILP sharing the weight registers)

typedef unsigned long long u64;

__device__ __forceinline__ u64 pk2(float lo, float hi) {
    u64 r; asm("mov.b64 %0, {%1,%2};" : "=l"(r) : "f"(lo), "f"(hi)); return r;
}
__device__ __forceinline__ void unpk2(u64 v, float& a, float& b) {
    asm("mov.b64 {%0,%1}, %2;" : "=f"(a), "=f"(b) : "l"(v));
}
// Packed f32x2 FMA (Blackwell full-rate path; ptxas never auto-fuses this)
__device__ __forceinline__ u64 ffma2(u64 a, u64 b, u64 c) {
    u64 d; asm("fma.rn.f32x2 %0, %1, %2, %3;" : "=l"(d) : "l"(a), "l"(b), "l"(c));
    return d;
}

// tanh with the 2*log2(e) factor pre-folded into the pre-activation:
// tanh(v) = 1 - 2/(exp(2v)+1) = 1 - 2*rcp(ex2(v') + 1),  v' = 2*log2(e)*v
__device__ __forceinline__ float tanh_scaled(float vp) {
    float e; asm("ex2.approx.f32 %0, %1;" : "=f"(e) : "f"(vp));
    float r; asm("rcp.approx.f32 %0, %1;" : "=f"(r) : "f"(e + 1.0f));
    return fmaf(-2.0f, r, 1.0f);
}

__global__ void __launch_bounds__(32, 1)
rnn2_kernel(const float* __restrict__ x,       // [B, T, 1]
            const float* __restrict__ hstate,  // [2, B, H]
            const float* __restrict__ Wih0,    // [H, 1]
            const float* __restrict__ Whh0,    // [H, H]
            const float* __restrict__ bih0, const float* __restrict__ bhh0,
            const float* __restrict__ Wih1,    // [H, H]
            const float* __restrict__ Whh1,    // [H, H]
            const float* __restrict__ bih1, const float* __restrict__ bhh1,
            const float* __restrict__ Wfc,     // [1, H]
            const float* __restrict__ bfc,     // [1]
            float* __restrict__ out)           // [B] pred ++ [2,B,H] h_new
{
    // [batch][buf][k] per layer — 128B rows; all lanes read the same 16B
    // (broadcast, conflict-free LDS.128); writes lane j -> word j.
    __shared__ __align__(16) float sh0[NB][2][HH];
    __shared__ __align__(16) float sh1[NB][2][HH];

    const int j  = threadIdx.x;          // 0..31, one warp per block
    const int b0 = blockIdx.x * NB;

    const float SC = 2.885390081777927f; // 2*log2(e), folded into weights

    // Weight rows for output neuron j, scaled, packed as f32x2 (k, k+1).
    u64 w0[16], wi1[16], wh1[16];
    {
        const float2* p = (const float2*)(Whh0 + j * HH);
        #pragma unroll
        for (int i = 0; i < 16; i++) { float2 f = p[i]; w0[i]  = pk2(f.x*SC, f.y*SC); }
        p = (const float2*)(Wih1 + j * HH);
        #pragma unroll
        for (int i = 0; i < 16; i++) { float2 f = p[i]; wi1[i] = pk2(f.x*SC, f.y*SC); }
        p = (const float2*)(Whh1 + j * HH);
        #pragma unroll
        for (int i = 0; i < 16; i++) { float2 f = p[i]; wh1[i] = pk2(f.x*SC, f.y*SC); }
    }
    const float wx0 = Wih0[j] * SC;
    const float bb0 = (bih0[j] + bhh0[j]) * SC;
    const float bb1 = (bih1[j] + bhh1[j]) * SC;

    // Initial hidden states -> buffer 0
    #pragma unroll
    for (int bi = 0; bi < NB; bi++) {
        sh0[bi][0][j] = hstate[(size_t)(b0 + bi) * HH + j];
        sh1[bi][0][j] = hstate[(size_t)BB * HH + (size_t)(b0 + bi) * HH + j];
    }
    __syncwarp();

    const float* xb[NB];
    float xv[NB];
    #pragma unroll
    for (int bi = 0; bi < NB; bi++) xb[bi] = x + (size_t)(b0 + bi) * TT;

    // ---- prologue: L0(0): h0'(0) = tanh(Whh0@h0 + Wih0*x0 + b) -> sh0[*][1]
    #pragma unroll
    for (int bi = 0; bi < NB; bi++) {
        u64 a = pk2(0.f, 0.f), ab = pk2(0.f, 0.f);
        const ulonglong2* hp = (const ulonglong2*)sh0[bi][0];
        #pragma unroll
        for (int i = 0; i < 8; i++) {
            ulonglong2 v = hp[i];
            a  = ffma2(w0[2*i],     v.x, a);
            ab = ffma2(w0[2*i + 1], v.y, ab);
        }
        float a0, a1, a2, a3;
        unpk2(a, a0, a1); unpk2(ab, a2, a3);
        sh0[bi][1][j] = tanh_scaled((a0 + a1) + (a2 + a3) + fmaf(wx0, xb[bi][0], bb0));
        xv[bi] = xb[bi][1];   // prefetch x[1]
    }
    __syncwarp();

    float h1n[NB];

    // ---- pipelined mainloop: phase t_e computes L0(t_e+1) and L1(t_e) ----
    // h0'(t) lives in sh0[buf (t+1)&1]; h1'(t) in sh1[buf (t+1)&1].
    #pragma unroll 1
    for (int t = 0; t < TT; t += 2) {
        #pragma unroll
        for (int s = 0; s < 2; s++) {     // t_e = t + s; compile-time parity
            const int rb0 = s ^ 1;        // h0'(t_e)
            const int wb0 = s;            // h0'(t_e+1)
            const int rb1 = s;            // h1'(t_e-1)
            const int wb1 = s ^ 1;        // h1'(t_e)

            u64 a0[NB], a0b[NB], a1[NB], a1b[NB], a1c[NB], a1d[NB];
            float xt[NB];
            #pragma unroll
            for (int bi = 0; bi < NB; bi++) {
                a0[bi] = a0b[bi] = a1[bi] = a1b[bi] = a1c[bi] = a1d[bi] = pk2(0.f, 0.f);
                xt[bi] = xv[bi];
                int tn = t + s + 2; if (tn > TT - 1) tn = TT - 1;
                xv[bi] = xb[bi][tn];
            }

            // One LDS.128 of h0'(t_e) feeds BOTH Whh0 (L0) and Wih1 (L1)
            #pragma unroll
            for (int i = 0; i < 8; i++) {
                #pragma unroll
                for (int bi = 0; bi < NB; bi++) {
                    ulonglong2 v = ((const ulonglong2*)sh0[bi][rb0])[i];
                    a0[bi]  = ffma2(w0[2*i],      v.x, a0[bi]);
                    a0b[bi] = ffma2(w0[2*i + 1],  v.y, a0b[bi]);
                    a1[bi]  = ffma2(wi1[2*i],     v.x, a1[bi]);
                    a1b[bi] = ffma2(wi1[2*i + 1], v.y, a1b[bi]);
                }
            }
            // Whh1 @ h1'(t_e-1)
            #pragma unroll
            for (int i = 0; i < 8; i++) {
                #pragma unroll
                for (int bi = 0; bi < NB; bi++) {
                    ulonglong2 u = ((const ulonglong2*)sh1[bi][rb1])[i];
                    a1c[bi] = ffma2(wh1[2*i],     u.x, a1c[bi]);
                    a1d[bi] = ffma2(wh1[2*i + 1], u.y, a1d[bi]);
                }
            }
            #pragma unroll
            for (int bi = 0; bi < NB; bi++) {
                float p0, p1, p2, p3, q0, q1, q2, q3;
                unpk2(a0[bi], p0, p1); unpk2(a0b[bi], p2, p3);
                sh0[bi][wb0][j] =
                    tanh_scaled((p0 + p1) + (p2 + p3) + fmaf(wx0, xt[bi], bb0));
                unpk2(a1[bi], q0, q1); unpk2(a1b[bi], q2, q3);
                float r0, r1, r2, r3;
                unpk2(a1c[bi], r0, r1); unpk2(a1d[bi], r2, r3);
                float pre1 = ((q0 + q1) + (q2 + q3)) + ((r0 + r1) + (r2 + r3)) + bb1;
                h1n[bi] = tanh_scaled(pre1);
                sh1[bi][wb1][j] = h1n[bi];
            }
            __syncwarp();
        }
    }

    // ---- outputs ----
    // h0'(TT-1) ended in sh0[*][TT&1 == 0]; h1'(TT-1) is h1n.
    #pragma unroll
    for (int bi = 0; bi < NB; bi++) {
        const size_t ob = (size_t)(b0 + bi) * HH + j;
        out[BB + ob]                   = sh0[bi][0][j];  // h_new[0]
        out[BB + (size_t)BB * HH + ob] = h1n[bi];        // h_new[1]

        float p = Wfc[j] * h1n[bi];
        #pragma unroll
        for (int off = 16; off; off >>= 1)
            p += __shfl_xor_sync(0xffffffffu, p, off);
        if (j == 0) out[b0 + bi] = p + bfc[0];
    }
}

extern "C" void kernel_launch(void* const* d_in, const int* in_sizes, int n_in,
                              void* d_out, int out_size) {
    const float* x     = (const float*)d_in[0];
    const float* hs    = (const float*)d_in[1];
    const float* Wih0  = (const float*)d_in[2];
    const float* Whh0  = (const float*)d_in[3];
    const float* bih0  = (const float*)d_in[4];
    const float* bhh0  = (const float*)d_in[5];
    const float* Wih1  = (const float*)d_in[6];
    const float* Whh1  = (const float*)d_in[7];
    const float* bih1  = (const float*)d_in[8];
    const float* bhh1  = (const float*)d_in[9];
    const float* Wfc   = (const float*)d_in[10];
    const float* bfc   = (const float*)d_in[11];
    float* out = (float*)d_out;

    rnn2_kernel<<<BB / NB, 32>>>(x, hs, Wih0, Whh0, bih0, bhh0,
                                 Wih1, Whh1, bih1, bhh1, Wfc, bfc, out);
}

// round 4
// speedup vs baseline: 1.4982x; 1.0080x over previous
#include <cuda_runtime.h>

#define BB 4096
#define TT 512
#define HH 32
#define NB 2      // batch streams per warp; grid = 2048 -> ~3.5 warps/SMSP resident

typedef unsigned long long u64;

__device__ __forceinline__ u64 pk2(float lo, float hi) {
    u64 r; asm("mov.b64 %0, {%1,%2};" : "=l"(r) : "f"(lo), "f"(hi)); return r;
}
__device__ __forceinline__ void unpk2(u64 v, float& a, float& b) {
    asm("mov.b64 {%0,%1}, %2;" : "=f"(a), "=f"(b) : "l"(v));
}
// Packed f32x2 FMA / ADD (Blackwell full-rate; ptxas never auto-fuses these)
__device__ __forceinline__ u64 ffma2(u64 a, u64 b, u64 c) {
    u64 d; asm("fma.rn.f32x2 %0, %1, %2, %3;" : "=l"(d) : "l"(a), "l"(b), "l"(c));
    return d;
}
__device__ __forceinline__ u64 fadd2(u64 a, u64 b) {
    u64 d; asm("add.rn.f32x2 %0, %1, %2;" : "=l"(d) : "l"(a), "l"(b));
    return d;
}

// tanh with 2*log2(e) pre-folded into the pre-activation:
// tanh(v) = 1 - 2*rcp(ex2(v') + 1),  v' = 2*log2(e)*v
__device__ __forceinline__ float tanh_scaled(float vp) {
    float e; asm("ex2.approx.f32 %0, %1;" : "=f"(e) : "f"(vp));
    float r; asm("rcp.approx.f32 %0, %1;" : "=f"(r) : "f"(e + 1.0f));
    return fmaf(-2.0f, r, 1.0f);
}

__global__ void __launch_bounds__(32)
rnn2_kernel(const float* __restrict__ x,       // [B, T, 1]
            const float* __restrict__ hstate,  // [2, B, H]
            const float* __restrict__ Wih0,    // [H, 1]
            const float* __restrict__ Whh0,    // [H, H]
            const float* __restrict__ bih0, const float* __restrict__ bhh0,
            const float* __restrict__ Wih1,    // [H, H]
            const float* __restrict__ Whh1,    // [H, H]
            const float* __restrict__ bih1, const float* __restrict__ bhh1,
            const float* __restrict__ Wfc,     // [1, H]
            const float* __restrict__ bfc,     // [1]
            float* __restrict__ out)           // [B] pred ++ [2,B,H] h_new
{
    // [batch][buf][k] per layer — 128B rows; all lanes read the same 16B
    // (broadcast, conflict-free LDS.128); writes lane j -> word j.
    __shared__ __align__(16) float sh0[NB][2][HH];
    __shared__ __align__(16) float sh1[NB][2][HH];

    const int j  = threadIdx.x;          // 0..31, one warp per block
    const int b0 = blockIdx.x * NB;

    const float SC = 2.885390081777927f; // 2*log2(e), folded into weights

    // Weight rows for output neuron j, scaled, packed as f32x2 (k, k+1).
    // 48 x u64 = 96 registers, shared by the NB batch streams.
    u64 w0[16], wi1[16], wh1[16];
    {
        const float2* p = (const float2*)(Whh0 + j * HH);
        #pragma unroll
        for (int i = 0; i < 16; i++) { float2 f = p[i]; w0[i]  = pk2(f.x*SC, f.y*SC); }
        p = (const float2*)(Wih1 + j * HH);
        #pragma unroll
        for (int i = 0; i < 16; i++) { float2 f = p[i]; wi1[i] = pk2(f.x*SC, f.y*SC); }
        p = (const float2*)(Whh1 + j * HH);
        #pragma unroll
        for (int i = 0; i < 16; i++) { float2 f = p[i]; wh1[i] = pk2(f.x*SC, f.y*SC); }
    }
    const float wx0 = Wih0[j] * SC;
    const float bb0 = (bih0[j] + bhh0[j]) * SC;
    const float bb1 = (bih1[j] + bhh1[j]) * SC;

    // Initial hidden states -> buffer 0
    #pragma unroll
    for (int bi = 0; bi < NB; bi++) {
        sh0[bi][0][j] = hstate[(size_t)(b0 + bi) * HH + j];
        sh1[bi][0][j] = hstate[(size_t)BB * HH + (size_t)(b0 + bi) * HH + j];
    }
    __syncwarp();

    const float* xb[NB];
    float xv[NB];
    #pragma unroll
    for (int bi = 0; bi < NB; bi++) xb[bi] = x + (size_t)(b0 + bi) * TT;

    // ---- prologue: L0(0): h0'(0) = tanh(Whh0@h0 + Wih0*x0 + b) -> sh0[*][1]
    #pragma unroll
    for (int bi = 0; bi < NB; bi++) {
        u64 a = pk2(0.f, 0.f), ab = pk2(0.f, 0.f);
        const ulonglong2* hp = (const ulonglong2*)sh0[bi][0];
        #pragma unroll
        for (int i = 0; i < 8; i++) {
            ulonglong2 v = hp[i];
            a  = ffma2(w0[2*i],     v.x, a);
            ab = ffma2(w0[2*i + 1], v.y, ab);
        }
        float lo, hi;
        unpk2(fadd2(a, ab), lo, hi);
        sh0[bi][1][j] = tanh_scaled(lo + hi + fmaf(wx0, xb[bi][0], bb0));
        xv[bi] = xb[bi][1];   // prefetch x[1]
    }
    __syncwarp();

    float h1n[NB];

    // ---- pipelined mainloop: phase t_e computes L0(t_e+1) and L1(t_e) ----
    #pragma unroll 1
    for (int t = 0; t < TT; t += 2) {
        #pragma unroll
        for (int s = 0; s < 2; s++) {     // t_e = t + s; compile-time parity
            const int rb0 = s ^ 1;        // h0'(t_e)
            const int wb0 = s;            // h0'(t_e+1)
            const int rb1 = s;            // h1'(t_e-1)
            const int wb1 = s ^ 1;        // h1'(t_e)

            int tn = t + s + 2; if (tn > TT - 1) tn = TT - 1;  // uniform clamp

            u64 a0[NB], a0b[NB], a1[NB], a1b[NB], a1c[NB], a1d[NB];
            float xt[NB];
            #pragma unroll
            for (int bi = 0; bi < NB; bi++) {
                a0[bi] = a0b[bi] = a1[bi] = a1b[bi] = a1c[bi] = a1d[bi] = pk2(0.f, 0.f);
                xt[bi] = xv[bi];
                xv[bi] = xb[bi][tn];
            }

            // One LDS.128 of h0'(t_e) feeds BOTH Whh0 (L0) and Wih1 (L1)
            #pragma unroll
            for (int i = 0; i < 8; i++) {
                #pragma unroll
                for (int bi = 0; bi < NB; bi++) {
                    ulonglong2 v = ((const ulonglong2*)sh0[bi][rb0])[i];
                    a0[bi]  = ffma2(w0[2*i],      v.x, a0[bi]);
                    a0b[bi] = ffma2(w0[2*i + 1],  v.y, a0b[bi]);
                    a1[bi]  = ffma2(wi1[2*i],     v.x, a1[bi]);
                    a1b[bi] = ffma2(wi1[2*i + 1], v.y, a1b[bi]);
                }
            }
            // Whh1 @ h1'(t_e-1)
            #pragma unroll
            for (int i = 0; i < 8; i++) {
                #pragma unroll
                for (int bi = 0; bi < NB; bi++) {
                    ulonglong2 u = ((const ulonglong2*)sh1[bi][rb1])[i];
                    a1c[bi] = ffma2(wh1[2*i],     u.x, a1c[bi]);
                    a1d[bi] = ffma2(wh1[2*i + 1], u.y, a1d[bi]);
                }
            }
            #pragma unroll
            for (int bi = 0; bi < NB; bi++) {
                float lo, hi;
                unpk2(fadd2(a0[bi], a0b[bi]), lo, hi);
                sh0[bi][wb0][j] =
                    tanh_scaled(lo + hi + fmaf(wx0, xt[bi], bb0));
                u64 s1 = fadd2(fadd2(a1[bi], a1b[bi]), fadd2(a1c[bi], a1d[bi]));
                unpk2(s1, lo, hi);
                h1n[bi] = tanh_scaled(lo + hi + bb1);
                sh1[bi][wb1][j] = h1n[bi];
            }
            __syncwarp();
        }
    }

    // ---- outputs ----
    // h0'(TT-1) ended in sh0[*][0]; h1'(TT-1) is h1n.
    #pragma unroll
    for (int bi = 0; bi < NB; bi++) {
        const size_t ob = (size_t)(b0 + bi) * HH + j;
        out[BB + ob]                   = sh0[bi][0][j];  // h_new[0]
        out[BB + (size_t)BB * HH + ob] = h1n[bi];        // h_new[1]

        float p = Wfc[j] * h1n[bi];
        #pragma unroll
        for (int off = 16; off; off >>= 1)
            p += __shfl_xor_sync(0xffffffffu, p, off);
        if (j == 0) out[b0 + bi] = p + bfc[0];
    }
}

extern "C" void kernel_launch(void* const* d_in, const int* in_sizes, int n_in,
                              void* d_out, int out_size) {
    const float* x     = (const float*)d_in[0];
    const float* hs    = (const float*)d_in[1];
    const float* Wih0  = (const float*)d_in[2];
    const float* Whh0  = (const float*)d_in[3];
    const float* bih0  = (const float*)d_in[4];
    const float* bhh0  = (const float*)d_in[5];
    const float* Wih1  = (const float*)d_in[6];
    const float* Whh1  = (const float*)d_in[7];
    const float* bih1  = (const float*)d_in[8];
    const float* bhh1  = (const float*)d_in[9];
    const float* Wfc   = (const float*)d_in[10];
    const float* bfc   = (const float*)d_in[11];
    float* out = (float*)d_out;

    rnn2_kernel<<<BB / NB, 32>>>(x, hs, Wih0, Whh0, bih0, bhh0,
                                 Wih1, Whh1, bih1, bhh1, Wfc, bfc, out);
}